// round 1
// baseline (speedup 1.0000x reference)
#include <cuda_runtime.h>
#include <math.h>

#define BB 64
#define TT 1024
#define JJ 128
#define DD 256
#define TILE_T 64
#define PJ 132   // sUT pitch in floats (transpose-write 4-way, read conflict-free, float2-aligned)
#define PT 68    // sHwT pitch in floats (16B aligned rows)

// scratch (no allocations allowed)
__device__ float g_su[BB * JJ];
__device__ float g_rowmax[BB * TT];
__device__ float g_q2c[BB * DD];

union F2U { float2 f; unsigned long long u; };

__device__ __forceinline__ float2 ffma2(float2 a, float2 b, float2 c) {
    F2U A, Bv, C, Dv;
    A.f = a; Bv.f = b; C.f = c;
    asm("fma.rn.f32x2 %0, %1, %2, %3;"
        : "=l"(Dv.u) : "l"(A.u), "l"(Bv.u), "l"(C.u));
    return Dv.f;
}

// ---------------- su[b][j] = U[b,j,:] . w_u ----------------
__global__ void su_kernel(const float* __restrict__ U, const float* __restrict__ w_u) {
    int b = blockIdx.x;
    int w = threadIdx.x >> 5, lane = threadIdx.x & 31;
    for (int r = 0; r < 16; r++) {
        int j = w * 16 + r;
        const float* Urow = U + ((size_t)(b * JJ + j)) * DD;
        float acc = 0.f;
        #pragma unroll
        for (int k = 0; k < 8; k++) {
            int d = lane + 32 * k;
            acc += Urow[d] * w_u[d];
        }
        #pragma unroll
        for (int o = 16; o; o >>= 1) acc += __shfl_xor_sync(0xffffffffu, acc, o);
        if (lane == 0) g_su[b * JJ + j] = acc;
    }
}

// ---------------- main fused kernel ----------------
// grid (T/TILE_T, B), 256 threads
__global__ void __launch_bounds__(256, 1)
bidaf_main(const float* __restrict__ H, const float* __restrict__ U,
           const float* __restrict__ w_h, const float* __restrict__ w_hu,
           float* __restrict__ G) {
    extern __shared__ float smem[];
    float* sUT  = smem;                     // [DD][PJ]   (GEMM1) -- later overlaid by sU2 [JJ][DD]
    float* sHwT = smem + DD * PJ;           // [DD][PT]   (GEMM1) -- later overlaid by sA [TILE_T][JJ]
    float* sA   = sHwT;
    float* sU2  = smem;
    float* ssh  = smem + DD * PJ + DD * PT; // [TILE_T]
    float* ssu  = ssh + TILE_T;             // [JJ]

    const int b  = blockIdx.y;
    const int t0 = blockIdx.x * TILE_T;
    const int tid = threadIdx.x;
    const int w = tid >> 5, lane = tid & 31;
    const int ty = lane >> 4;     // 0/1 t-subgroup within warp
    const int lx = lane & 15;     // j(or d)-lane index within 16-lane group

    // ---- Phase A: stage U^T ----
    for (int jj = 0; jj < 16; jj++) {
        int j = w * 16 + jj;
        const float* Urow = U + ((size_t)(b * JJ + j)) * DD;
        #pragma unroll
        for (int k = 0; k < 8; k++) {
            int d = lane + 32 * k;
            sUT[d * PJ + j] = Urow[d];
        }
    }
    // ---- Phase A: stage Hw^T and sh ----
    for (int i = 0; i < 8; i++) {
        int tl = w * 8 + i;
        const float* Hrow = H + ((size_t)(b * TT + t0 + tl)) * DD;
        float shacc = 0.f;
        #pragma unroll
        for (int k = 0; k < 8; k++) {
            int d = lane + 32 * k;
            float h = Hrow[d];
            sHwT[d * PT + tl] = h * w_hu[d];
            shacc += h * w_h[d];
        }
        #pragma unroll
        for (int o = 16; o; o >>= 1) shacc += __shfl_xor_sync(0xffffffffu, shacc, o);
        if (lane == 0) ssh[tl] = shacc;
    }
    if (tid < JJ) ssu[tid] = g_su[b * JJ + tid];
    __syncthreads();

    // ---- GEMM1: S[t][j] = sum_d Hw[t][d] * U[j][d] ----
    // thread: t = tb..tb+3 (tb = 8w + 4ty), j pairs (2lx + 32q2, +1), q2=0..3
    const int tb = w * 8 + ty * 4;
    const int jb = 2 * lx;
    float2 acc[4][4];
    #pragma unroll
    for (int i = 0; i < 4; i++)
        #pragma unroll
        for (int q = 0; q < 4; q++) acc[i][q] = make_float2(0.f, 0.f);

    #pragma unroll 4
    for (int d = 0; d < DD; d++) {
        float4 a4 = *(const float4*)&sHwT[d * PT + tb];
        const float* ur = &sUT[d * PJ + jb];
        float2 b0 = *(const float2*)(ur);
        float2 b1 = *(const float2*)(ur + 32);
        float2 b2 = *(const float2*)(ur + 64);
        float2 b3 = *(const float2*)(ur + 96);
        float av[4] = {a4.x, a4.y, a4.z, a4.w};
        #pragma unroll
        for (int i = 0; i < 4; i++) {
            float2 ad = make_float2(av[i], av[i]);
            acc[i][0] = ffma2(ad, b0, acc[i][0]);
            acc[i][1] = ffma2(ad, b1, acc[i][1]);
            acc[i][2] = ffma2(ad, b2, acc[i][2]);
            acc[i][3] = ffma2(ad, b3, acc[i][3]);
        }
    }

    // ---- softmax over j (per row, across the 16-lane group) ----
    #pragma unroll
    for (int i = 0; i < 4; i++) {
        int tl = tb + i;
        float2 s[4];
        float m = -1e30f;
        #pragma unroll
        for (int q = 0; q < 4; q++) {
            float2 suv = *(const float2*)&ssu[jb + 32 * q];
            s[q].x = acc[i][q].x + suv.x;
            s[q].y = acc[i][q].y + suv.y;
            m = fmaxf(m, fmaxf(s[q].x, s[q].y));
        }
        #pragma unroll
        for (int o = 8; o; o >>= 1) m = fmaxf(m, __shfl_xor_sync(0xffffffffu, m, o));
        float sum = 0.f;
        #pragma unroll
        for (int q = 0; q < 4; q++) {
            s[q].x = __expf(s[q].x - m);
            s[q].y = __expf(s[q].y - m);
            sum += s[q].x + s[q].y;
        }
        #pragma unroll
        for (int o = 8; o; o >>= 1) sum += __shfl_xor_sync(0xffffffffu, sum, o);
        float inv = 1.f / sum;
        if (lx == 0) g_rowmax[b * TT + t0 + tl] = m + ssh[tl]; // true max_j S (sh is row-constant)
        #pragma unroll
        for (int q = 0; q < 4; q++) {
            acc[i][q].x = s[q].x * inv;
            acc[i][q].y = s[q].y * inv;
        }
    }
    __syncthreads();  // everyone done reading sHwT/sUT

    // ---- write A, stage U row-major (overlays) ----
    #pragma unroll
    for (int i = 0; i < 4; i++)
        #pragma unroll
        for (int q = 0; q < 4; q++)
            *(float2*)&sA[(tb + i) * JJ + jb + 32 * q] = acc[i][q];

    {
        const float4* Ug4 = (const float4*)(U + (size_t)b * JJ * DD);
        float4* sU4 = (float4*)sU2;
        #pragma unroll
        for (int it = 0; it < 32; it++) {
            int idx = tid + 256 * it;   // 8192 float4 total
            sU4[idx] = Ug4[idx];
        }
    }
    __syncthreads();

    // ---- GEMM2: C2Q[t][d] = sum_j A[t][j] * U[j][d] ----
    // thread: t = tb..tb+3, d pairs (2lx + 32e, +1), e=0..7
    const int db = 2 * lx;
    float2 c[4][8];
    #pragma unroll
    for (int i = 0; i < 4; i++)
        #pragma unroll
        for (int e = 0; e < 8; e++) c[i][e] = make_float2(0.f, 0.f);

    #pragma unroll 2
    for (int j = 0; j < JJ; j++) {
        float a0 = sA[(tb + 0) * JJ + j];
        float a1 = sA[(tb + 1) * JJ + j];
        float a2 = sA[(tb + 2) * JJ + j];
        float a3 = sA[(tb + 3) * JJ + j];
        const float* ur = sU2 + j * DD + db;
        float2 bv[8];
        #pragma unroll
        for (int e = 0; e < 8; e++) bv[e] = *(const float2*)(ur + 32 * e);
        float av[4] = {a0, a1, a2, a3};
        #pragma unroll
        for (int i = 0; i < 4; i++) {
            float2 ad = make_float2(av[i], av[i]);
            #pragma unroll
            for (int e = 0; e < 8; e++)
                c[i][e] = ffma2(ad, bv[e], c[i][e]);
        }
    }

    // ---- epilogue: G[:,0:D]=H, [D:2D]=C2Q, [2D:3D]=H*C2Q ----
    #pragma unroll
    for (int i = 0; i < 4; i++) {
        int tl = tb + i;
        const float* Hrow = H + ((size_t)(b * TT + t0 + tl)) * DD;
        float* Grow = G + ((size_t)(b * TT + t0 + tl)) * (4 * DD);
        #pragma unroll
        for (int e = 0; e < 8; e++) {
            int d = db + 32 * e;
            float2 h = *(const float2*)&Hrow[d];
            float2 cq = c[i][e];
            *(float2*)&Grow[d] = h;
            *(float2*)&Grow[DD + d] = cq;
            *(float2*)&Grow[2 * DD + d] = make_float2(h.x * cq.x, h.y * cq.y);
        }
    }
}

// ---------------- Q2C: b_att = softmax_t(max_j S), Q2C[b,d] = sum_t b_att H ----------------
__global__ void q2c_kernel(const float* __restrict__ H) {
    __shared__ float sb[TT];
    __shared__ float red[8];
    int b = blockIdx.x;
    int tid = threadIdx.x;           // 256
    int w = tid >> 5, lane = tid & 31;

    float v[4];
    float m = -1e30f;
    #pragma unroll
    for (int k = 0; k < 4; k++) {
        v[k] = g_rowmax[b * TT + tid + 256 * k];
        m = fmaxf(m, v[k]);
    }
    #pragma unroll
    for (int o = 16; o; o >>= 1) m = fmaxf(m, __shfl_xor_sync(0xffffffffu, m, o));
    if (lane == 0) red[w] = m;
    __syncthreads();
    float M = red[0];
    #pragma unroll
    for (int i = 1; i < 8; i++) M = fmaxf(M, red[i]);
    __syncthreads();

    float sum = 0.f;
    #pragma unroll
    for (int k = 0; k < 4; k++) {
        float e = __expf(v[k] - M);
        sb[tid + 256 * k] = e;
        sum += e;
    }
    #pragma unroll
    for (int o = 16; o; o >>= 1) sum += __shfl_xor_sync(0xffffffffu, sum, o);
    if (lane == 0) red[w] = sum;
    __syncthreads();
    float S = 0.f;
    #pragma unroll
    for (int i = 0; i < 8; i++) S += red[i];
    float inv = 1.f / S;
    __syncthreads();

    // d = tid
    const float* Hb = H + (size_t)b * TT * DD + tid;
    float q = 0.f;
    #pragma unroll 8
    for (int t = 0; t < TT; t++) q += sb[t] * Hb[(size_t)t * DD];
    g_q2c[b * DD + tid] = q * inv;
}

// ---------------- last quarter: G[:,3D:4D] = H * Q2C ----------------
__global__ void g3_kernel(const float* __restrict__ H, float* __restrict__ G) {
    size_t idx = (size_t)blockIdx.x * 256 + threadIdx.x;  // float2 units over B*T*D/2
    int d2 = (int)(idx & 127);        // D/2 = 128 float2 per row
    size_t bt = idx >> 7;
    int b = (int)(bt >> 10);
    float2 h = ((const float2*)H)[idx];
    float2 q = ((const float2*)g_q2c)[b * 128 + d2];
    float2 o = make_float2(h.x * q.x, h.y * q.y);
    ((float2*)G)[bt * 512 + 384 + d2] = o;   // row = 512 float2, quarter-3 at 384
}

extern "C" void kernel_launch(void* const* d_in, const int* in_sizes, int n_in,
                              void* d_out, int out_size) {
    const float* H    = (const float*)d_in[0];
    const float* U    = (const float*)d_in[1];
    const float* w_h  = (const float*)d_in[2];
    const float* w_u  = (const float*)d_in[3];
    const float* w_hu = (const float*)d_in[4];
    float* G = (float*)d_out;

    const int smem_bytes = (DD * PJ + DD * PT + TILE_T + JJ) * (int)sizeof(float);
    cudaFuncSetAttribute(bidaf_main, cudaFuncAttributeMaxDynamicSharedMemorySize, smem_bytes);

    su_kernel<<<BB, 256>>>(U, w_u);
    bidaf_main<<<dim3(TT / TILE_T, BB), 256, smem_bytes>>>(H, U, w_h, w_hu, G);
    q2c_kernel<<<BB, 256>>>(H);
    g3_kernel<<<(BB * TT * DD / 2) / 256, 256>>>(H, G);
}

// round 6
// speedup vs baseline: 1.4695x; 1.4695x over previous
#include <cuda_runtime.h>
#include <cuda_bf16.h>
#include <cstdint>
#include <math.h>

#define BB 64
#define TT 1024
#define JJ 128
#define DD 256
#define TM 128   // t rows per CTA tile

// ---------------- device scratch (no runtime alloc allowed) ----------------
__device__ __align__(16) __nv_bfloat16 g_Uhi[BB * JJ * DD];
__device__ __align__(16) __nv_bfloat16 g_Ulo[BB * JJ * DD];
__device__ __align__(16) __nv_bfloat16 g_UThi[BB * DD * JJ];
__device__ __align__(16) __nv_bfloat16 g_UTlo[BB * DD * JJ];
__device__ float g_su[BB * JJ];
__device__ float g_rowmax[BB * TT];
__device__ float g_q2c[BB * DD];

__device__ __forceinline__ void bsplit(float v, uint16_t& hi, uint16_t& lo) {
    __nv_bfloat16 h = __float2bfloat16(v);
    hi = __bfloat16_as_ushort(h);
    lo = __bfloat16_as_ushort(__float2bfloat16(v - __bfloat162float(h)));
}

// mma.sync m16n8k16 bf16 -> f32 (standard sm_80+ PTX; maps to HMMA on sm_103)
__device__ __forceinline__ void mma16816(float* c, const uint32_t* a, const uint32_t* b) {
    asm volatile(
        "mma.sync.aligned.m16n8k16.row.col.f32.bf16.bf16.f32 "
        "{%0,%1,%2,%3}, {%4,%5,%6,%7}, {%8,%9}, {%0,%1,%2,%3};"
        : "+f"(c[0]), "+f"(c[1]), "+f"(c[2]), "+f"(c[3])
        : "r"(a[0]), "r"(a[1]), "r"(a[2]), "r"(a[3]), "r"(b[0]), "r"(b[1]));
}

// ---------------- smem layout (bytes) ----------------
// bf16 tiles use pitch 136 elements (272B): frag loads are bank-conflict-free.
#define SA_H 0u          // [128][136] bf16  (A operand hi; later prob hi)
#define SA_L 34816u      // [128][136] bf16  (A lo / prob lo)
#define SB_H 69632u      // [256][136] bf16  (U chunk hi / UT hi / epi f32 buffer)
#define SB_L 139264u     // [256][136] bf16  (U chunk lo / UT lo)
#define OFF_SSU 208896u  // [128] f32
#define OFF_SSH 209408u  // [128] f32
#define OFF_RM  209920u  // [128][2] f32
#define OFF_RS  210944u  // [128][2] f32
#define OFF_WHU 211968u  // [256] f32
#define OFF_WH  212992u  // [256] f32
#define SMEM_TOTAL 214016u

// ---------------- U split + transpose + su precompute ----------------
__global__ void usplit_kernel(const float* __restrict__ U, const float* __restrict__ w_u) {
    __shared__ float sT[8][32][33];
    __shared__ float sSu[32];
    int b = blockIdx.x >> 2, jt = blockIdx.x & 3;
    int w = threadIdx.x >> 5, lane = threadIdx.x & 31;
    const float* Ub = U + (size_t)b * JJ * DD;
    __nv_bfloat16* uh = g_Uhi + (size_t)b * JJ * DD;
    __nv_bfloat16* ul = g_Ulo + (size_t)b * JJ * DD;
    __nv_bfloat16* th = g_UThi + (size_t)b * DD * JJ;
    __nv_bfloat16* tl = g_UTlo + (size_t)b * DD * JJ;
    if (threadIdx.x < 32) sSu[threadIdx.x] = 0.f;
    __syncthreads();
    for (int r = 0; r < 32; r++) {
        int j = jt * 32 + r, d = w * 32 + lane;
        float v = Ub[j * DD + d];
        uint16_t hi, lo; bsplit(v, hi, lo);
        uh[j * DD + d] = __ushort_as_bfloat16(hi);
        ul[j * DD + d] = __ushort_as_bfloat16(lo);
        sT[w][r][lane] = v;
        float p = v * w_u[d];
        #pragma unroll
        for (int o = 16; o; o >>= 1) p += __shfl_xor_sync(0xffffffffu, p, o);
        if (lane == 0) atomicAdd(&sSu[r], p);
    }
    __syncthreads();
    if (threadIdx.x < 32) g_su[b * JJ + jt * 32 + threadIdx.x] = sSu[threadIdx.x];
    for (int rr = 0; rr < 32; rr++) {
        int d = w * 32 + rr, j = jt * 32 + lane;
        float v = sT[w][lane][rr];
        uint16_t hi, lo; bsplit(v, hi, lo);
        th[d * JJ + j] = __ushort_as_bfloat16(hi);
        tl[d * JJ + j] = __ushort_as_bfloat16(lo);
    }
}

// ---------------- main fused kernel: HMMA GEMMs + softmax + epilogue ----------------
__global__ void __launch_bounds__(256, 1)
bidaf_main(const float* __restrict__ H, const float* __restrict__ w_h,
           const float* __restrict__ w_hu, float* __restrict__ G) {
    extern __shared__ char smem[];
    const int b = blockIdx.y;
    const int t0 = blockIdx.x * TM;
    const int tid = threadIdx.x;
    const int wid = tid >> 5, lane = tid & 31;
    const int g = lane >> 2, qt = lane & 3;

    float* sWhu = (float*)(smem + OFF_WHU);
    float* sWh  = (float*)(smem + OFF_WH);
    float* ssu  = (float*)(smem + OFF_SSU);
    float* ssh  = (float*)(smem + OFF_SSH);
    float* sRM  = (float*)(smem + OFF_RM);
    float* sRS  = (float*)(smem + OFF_RS);

    sWhu[tid] = w_hu[tid];
    sWh[tid]  = w_h[tid];
    if (tid < JJ) ssu[tid] = g_su[b * JJ + tid];

    // ================= GEMM1: S[128t][128j], K=256 in 2 chunks =================
    const int wm1 = wid >> 1, wn1 = wid & 1;   // 4x2 warp grid, 32x64 tiles
    float C1[2][8][4];
    #pragma unroll
    for (int mf = 0; mf < 2; mf++)
        #pragma unroll
        for (int nf = 0; nf < 8; nf++)
            #pragma unroll
            for (int q = 0; q < 4; q++) C1[mf][nf][q] = 0.f;

    float shreg[16];
    #pragma unroll
    for (int k = 0; k < 16; k++) shreg[k] = 0.f;

    __syncthreads();   // sWhu/sWh ready

    for (int ch = 0; ch < 2; ch++) {
        const int d0 = ch * 128;
        // --- stage A = H*w_hu hi/lo chunk ---
        {
            const float4* H4 = (const float4*)(H + ((size_t)(b * TT + t0)) * DD);
            #pragma unroll
            for (int k = 0; k < 16; k++) {
                int row = wid + 8 * k;
                int c4 = (tid + 256 * k) & 31;
                int d = d0 + c4 * 4;
                float4 v = H4[row * 64 + (d >> 2)];
                float a0 = v.x * sWhu[d],     a1 = v.y * sWhu[d + 1];
                float a2 = v.z * sWhu[d + 2], a3 = v.w * sWhu[d + 3];
                uint16_t h0,l0,h1,l1,h2,l2,h3,l3;
                bsplit(a0,h0,l0); bsplit(a1,h1,l1); bsplit(a2,h2,l2); bsplit(a3,h3,l3);
                uint32_t off = (uint32_t)row * 272u + (uint32_t)c4 * 8u;
                *(uint2*)(smem + SA_H + off) = make_uint2((uint32_t)h0 | ((uint32_t)h1 << 16),
                                                          (uint32_t)h2 | ((uint32_t)h3 << 16));
                *(uint2*)(smem + SA_L + off) = make_uint2((uint32_t)l0 | ((uint32_t)l1 << 16),
                                                          (uint32_t)l2 | ((uint32_t)l3 << 16));
                float sh = v.x * sWh[d] + v.y * sWh[d + 1] + v.z * sWh[d + 2] + v.w * sWh[d + 3];
                #pragma unroll
                for (int o = 16; o; o >>= 1) sh += __shfl_xor_sync(0xffffffffu, sh, o);
                shreg[k] += sh;
            }
        }
        // --- stage U chunk hi/lo ---
        {
            const uint4* Uh4 = (const uint4*)(g_Uhi + (size_t)b * JJ * DD);
            const uint4* Ul4 = (const uint4*)(g_Ulo + (size_t)b * JJ * DD);
            #pragma unroll
            for (int k = 0; k < 8; k++) {
                int idx = tid + 256 * k;
                int row = idx >> 4, c8 = idx & 15;
                int gi = row * 32 + (d0 >> 3) + c8;
                uint32_t off = (uint32_t)row * 272u + (uint32_t)c8 * 16u;
                *(uint4*)(smem + SB_H + off) = Uh4[gi];
                *(uint4*)(smem + SB_L + off) = Ul4[gi];
            }
        }
        __syncthreads();

        const uint32_t* WAH = (const uint32_t*)(smem + SA_H);
        const uint32_t* WAL = (const uint32_t*)(smem + SA_L);
        const uint32_t* WBH = (const uint32_t*)(smem + SB_H);
        const uint32_t* WBL = (const uint32_t*)(smem + SB_L);
        #pragma unroll
        for (int ks = 0; ks < 8; ks++) {
            uint32_t aH[2][4], aL[2][4];
            #pragma unroll
            for (int mf = 0; mf < 2; mf++) {
                int r = wm1 * 32 + mf * 16 + g;
                int w0 = r * 68 + ks * 8 + qt;
                aH[mf][0] = WAH[w0];           aH[mf][1] = WAH[w0 + 544];
                aH[mf][2] = WAH[w0 + 4];       aH[mf][3] = WAH[w0 + 548];
                aL[mf][0] = WAL[w0];           aL[mf][1] = WAL[w0 + 544];
                aL[mf][2] = WAL[w0 + 4];       aL[mf][3] = WAL[w0 + 548];
            }
            uint32_t bH[8][2], bL[8][2];
            #pragma unroll
            for (int nf = 0; nf < 8; nf++) {
                int n = wn1 * 64 + nf * 8 + g;
                int w0 = n * 68 + ks * 8 + qt;
                bH[nf][0] = WBH[w0]; bH[nf][1] = WBH[w0 + 4];
                bL[nf][0] = WBL[w0]; bL[nf][1] = WBL[w0 + 4];
            }
            #pragma unroll
            for (int mf = 0; mf < 2; mf++)
                #pragma unroll
                for (int nf = 0; nf < 8; nf++) {
                    mma16816(C1[mf][nf], aH[mf], bH[nf]);
                    mma16816(C1[mf][nf], aL[mf], bH[nf]);
                    mma16816(C1[mf][nf], aH[mf], bL[nf]);
                }
        }
        __syncthreads();
    }
    if (lane == 0) {
        #pragma unroll
        for (int k = 0; k < 16; k++) ssh[wid + 8 * k] = shreg[k];
    }

    // --- stage U^T hi/lo into SB (full [256][128]) ---
    {
        const uint4* Th4 = (const uint4*)(g_UThi + (size_t)b * DD * JJ);
        const uint4* Tl4 = (const uint4*)(g_UTlo + (size_t)b * DD * JJ);
        #pragma unroll
        for (int k = 0; k < 16; k++) {
            int idx = tid + 256 * k;
            int row = idx >> 4, c8 = idx & 15;
            uint32_t off = (uint32_t)row * 272u + (uint32_t)c8 * 16u;
            *(uint4*)(smem + SB_H + off) = Th4[idx];
            *(uint4*)(smem + SB_L + off) = Tl4[idx];
        }
    }

    // ================= softmax over j =================
    // pass 1: add su, row max
    #pragma unroll
    for (int mf = 0; mf < 2; mf++) {
        int r0 = wm1 * 32 + mf * 16 + g;
        float m0 = -1e30f, m1 = -1e30f;
        #pragma unroll
        for (int nf = 0; nf < 8; nf++) {
            float2 su2 = *(const float2*)&ssu[wn1 * 64 + nf * 8 + qt * 2];
            C1[mf][nf][0] += su2.x; C1[mf][nf][1] += su2.y;
            C1[mf][nf][2] += su2.x; C1[mf][nf][3] += su2.y;
            m0 = fmaxf(m0, fmaxf(C1[mf][nf][0], C1[mf][nf][1]));
            m1 = fmaxf(m1, fmaxf(C1[mf][nf][2], C1[mf][nf][3]));
        }
        #pragma unroll
        for (int o = 1; o < 4; o <<= 1) {
            m0 = fmaxf(m0, __shfl_xor_sync(0xffffffffu, m0, o));
            m1 = fmaxf(m1, __shfl_xor_sync(0xffffffffu, m1, o));
        }
        if (qt == 0) { sRM[r0 * 2 + wn1] = m0; sRM[(r0 + 8) * 2 + wn1] = m1; }
    }
    __syncthreads();
    // pass 2: exp + sums, rowmax out
    #pragma unroll
    for (int mf = 0; mf < 2; mf++) {
        int r0 = wm1 * 32 + mf * 16 + g;
        float M0 = fmaxf(sRM[r0 * 2], sRM[r0 * 2 + 1]);
        float M1 = fmaxf(sRM[(r0 + 8) * 2], sRM[(r0 + 8) * 2 + 1]);
        float s0 = 0.f, s1 = 0.f;
        #pragma unroll
        for (int nf = 0; nf < 8; nf++) {
            C1[mf][nf][0] = __expf(C1[mf][nf][0] - M0);
            C1[mf][nf][1] = __expf(C1[mf][nf][1] - M0);
            C1[mf][nf][2] = __expf(C1[mf][nf][2] - M1);
            C1[mf][nf][3] = __expf(C1[mf][nf][3] - M1);
            s0 += C1[mf][nf][0] + C1[mf][nf][1];
            s1 += C1[mf][nf][2] + C1[mf][nf][3];
        }
        #pragma unroll
        for (int o = 1; o < 4; o <<= 1) {
            s0 += __shfl_xor_sync(0xffffffffu, s0, o);
            s1 += __shfl_xor_sync(0xffffffffu, s1, o);
        }
        if (qt == 0) {
            sRS[r0 * 2 + wn1] = s0; sRS[(r0 + 8) * 2 + wn1] = s1;
            if (wn1 == 0) {
                g_rowmax[b * TT + t0 + r0]     = M0 + ssh[r0];
                g_rowmax[b * TT + t0 + r0 + 8] = M1 + ssh[r0 + 8];
            }
        }
    }
    __syncthreads();
    // pass 3: normalize + pack bf16 hi/lo into SA (probabilities [t][j])
    #pragma unroll
    for (int mf = 0; mf < 2; mf++) {
        int r0 = wm1 * 32 + mf * 16 + g;
        float inv0 = 1.f / (sRS[r0 * 2] + sRS[r0 * 2 + 1]);
        float inv1 = 1.f / (sRS[(r0 + 8) * 2] + sRS[(r0 + 8) * 2 + 1]);
        #pragma unroll
        for (int nf = 0; nf < 8; nf++) {
            int col = wn1 * 64 + nf * 8 + qt * 2;
            float p00 = C1[mf][nf][0] * inv0, p01 = C1[mf][nf][1] * inv0;
            float p10 = C1[mf][nf][2] * inv1, p11 = C1[mf][nf][3] * inv1;
            uint16_t h0,l0,h1,l1,h2,l2,h3,l3;
            bsplit(p00,h0,l0); bsplit(p01,h1,l1); bsplit(p10,h2,l2); bsplit(p11,h3,l3);
            uint32_t o0 = (uint32_t)r0 * 272u + (uint32_t)col * 2u;
            uint32_t o1 = (uint32_t)(r0 + 8) * 272u + (uint32_t)col * 2u;
            *(uint32_t*)(smem + SA_H + o0) = (uint32_t)h0 | ((uint32_t)h1 << 16);
            *(uint32_t*)(smem + SA_L + o0) = (uint32_t)l0 | ((uint32_t)l1 << 16);
            *(uint32_t*)(smem + SA_H + o1) = (uint32_t)h2 | ((uint32_t)h3 << 16);
            *(uint32_t*)(smem + SA_L + o1) = (uint32_t)l2 | ((uint32_t)l3 << 16);
        }
    }
    __syncthreads();

    // ================= GEMM2: C2Q[128t][256d], K=128 =================
    const int wm2 = wid >> 2, wn2 = wid & 3;   // 2x4 warp grid, 64x64 tiles
    float C2[4][8][4];
    #pragma unroll
    for (int mf = 0; mf < 4; mf++)
        #pragma unroll
        for (int nf = 0; nf < 8; nf++)
            #pragma unroll
            for (int q = 0; q < 4; q++) C2[mf][nf][q] = 0.f;

    {
        const uint32_t* PAH = (const uint32_t*)(smem + SA_H);
        const uint32_t* PAL = (const uint32_t*)(smem + SA_L);
        const uint32_t* PBH = (const uint32_t*)(smem + SB_H);
        const uint32_t* PBL = (const uint32_t*)(smem + SB_L);
        #pragma unroll
        for (int ks = 0; ks < 8; ks++) {
            uint32_t bH[8][2], bL[8][2];
            #pragma unroll
            for (int nf = 0; nf < 8; nf++) {
                int n = wn2 * 64 + nf * 8 + g;
                int w0 = n * 68 + ks * 8 + qt;
                bH[nf][0] = PBH[w0]; bH[nf][1] = PBH[w0 + 4];
                bL[nf][0] = PBL[w0]; bL[nf][1] = PBL[w0 + 4];
            }
            #pragma unroll
            for (int mf = 0; mf < 4; mf++) {
                int r = wm2 * 64 + mf * 16 + g;
                int w0 = r * 68 + ks * 8 + qt;
                uint32_t aH[4] = {PAH[w0], PAH[w0 + 544], PAH[w0 + 4], PAH[w0 + 548]};
                uint32_t aL[4] = {PAL[w0], PAL[w0 + 544], PAL[w0 + 4], PAL[w0 + 548]};
                #pragma unroll
                for (int nf = 0; nf < 8; nf++) {
                    mma16816(C2[mf][nf], aH, bH[nf]);
                    mma16816(C2[mf][nf], aL, bH[nf]);
                    mma16816(C2[mf][nf], aH, bL[nf]);
                }
            }
        }
    }
    __syncthreads();   // done reading SB -> reuse as fp32 epilogue buffer

    // ================= epilogue =================
    {
        float* sEpi = (float*)(smem + SB_H);   // [128][264] f32
        #pragma unroll
        for (int mf = 0; mf < 4; mf++) {
            int r0 = wm2 * 64 + mf * 16 + g;
            #pragma unroll
            for (int nf = 0; nf < 8; nf++) {
                int c0 = wn2 * 64 + nf * 8 + qt * 2;
                *(float2*)&sEpi[r0 * 264 + c0]       = make_float2(C2[mf][nf][0], C2[mf][nf][1]);
                *(float2*)&sEpi[(r0 + 8) * 264 + c0] = make_float2(C2[mf][nf][2], C2[mf][nf][3]);
            }
        }
        __syncthreads();
        #pragma unroll 2
        for (int r = 0; r < 16; r++) {
            int row = wid * 16 + r;
            size_t rowg = (size_t)(b * TT + t0 + row);
            const float* Hrow = H + rowg * DD;
            float* Grow = G + rowg * (4 * DD);
            #pragma unroll
            for (int i = 0; i < 4; i++) {
                int d = 2 * lane + 64 * i;
                float2 cq = *(float2*)&sEpi[row * 264 + d];
                float2 h = *(const float2*)&Hrow[d];
                *(float2*)&Grow[d] = h;
                *(float2*)&Grow[DD + d] = cq;
                *(float2*)&Grow[2 * DD + d] = make_float2(h.x * cq.x, h.y * cq.y);
            }
        }
    }
}

// ---------------- Q2C: b_att = softmax_t(max_j S), Q2C[b,d] = sum_t b_att H ----------------
__global__ void q2c_kernel(const float* __restrict__ H) {
    __shared__ float sb[TT];
    __shared__ float red[8];
    int b = blockIdx.x;
    int tid = threadIdx.x;
    int w = tid >> 5, lane = tid & 31;

    float v[4];
    float m = -1e30f;
    #pragma unroll
    for (int k = 0; k < 4; k++) { v[k] = g_rowmax[b * TT + tid + 256 * k]; m = fmaxf(m, v[k]); }
    #pragma unroll
    for (int o = 16; o; o >>= 1) m = fmaxf(m, __shfl_xor_sync(0xffffffffu, m, o));
    if (lane == 0) red[w] = m;
    __syncthreads();
    float M = red[0];
    #pragma unroll
    for (int i = 1; i < 8; i++) M = fmaxf(M, red[i]);
    __syncthreads();

    float sum = 0.f;
    #pragma unroll
    for (int k = 0; k < 4; k++) { float e = __expf(v[k] - M); sb[tid + 256 * k] = e; sum += e; }
    #pragma unroll
    for (int o = 16; o; o >>= 1) sum += __shfl_xor_sync(0xffffffffu, sum, o);
    if (lane == 0) red[w] = sum;
    __syncthreads();
    float S = 0.f;
    #pragma unroll
    for (int i = 0; i < 8; i++) S += red[i];
    float inv = 1.f / S;
    __syncthreads();

    const float* Hb = H + (size_t)b * TT * DD + tid;
    float q = 0.f;
    #pragma unroll 8
    for (int t = 0; t < TT; t++) q += sb[t] * Hb[(size_t)t * DD];
    g_q2c[b * DD + tid] = q * inv;
}

// ---------------- last quarter: G[:,3D:4D] = H * Q2C ----------------
__global__ void g3_kernel(const float* __restrict__ H, float* __restrict__ G) {
    size_t idx = (size_t)blockIdx.x * 256 + threadIdx.x;  // float4 units
    int d4 = (int)(idx & 63);
    size_t bt = idx >> 6;
    int b = (int)(bt >> 10);
    float4 h = ((const float4*)H)[idx];
    float4 q = ((const float4*)g_q2c)[b * 64 + d4];
    float4 o = make_float4(h.x * q.x, h.y * q.y, h.z * q.z, h.w * q.w);
    ((float4*)G)[bt * 256 + 192 + d4] = o;
}

extern "C" void kernel_launch(void* const* d_in, const int* in_sizes, int n_in,
                              void* d_out, int out_size) {
    const float* H    = (const float*)d_in[0];
    const float* U    = (const float*)d_in[1];
    const float* w_h  = (const float*)d_in[2];
    const float* w_u  = (const float*)d_in[3];
    const float* w_hu = (const float*)d_in[4];
    float* G = (float*)d_out;

    cudaFuncSetAttribute(bidaf_main, cudaFuncAttributeMaxDynamicSharedMemorySize, SMEM_TOTAL);

    usplit_kernel<<<BB * 4, 256>>>(U, w_u);
    bidaf_main<<<dim3(TT / TM, BB), 256, SMEM_TOTAL>>>(H, w_h, w_hu, G);
    q2c_kernel<<<BB, 256>>>(H);
    g3_kernel<<<(BB * TT * DD / 4) / 256, 256>>>(H, G);
}